// round 7
// baseline (speedup 1.0000x reference)
#include <cuda_runtime.h>

// ZNCC fused, warp-per-channel sliding-window version (R5 pipeline) with
// 2-deep software prefetch and pointer-increment addressing.
// CTA = 96 threads = 3 warps; warp w handles channel w of one
// (batch, strip, col-group) tile: 64 raw cols (2/lane) x 32 output rows.
// Per-channel NCC rows -> smem plane; one __syncthreads; fixed-order combine.
//
// math per pixel (zero-padded 5x5 means):
//   mx = box(x), my = box(y); xc = x-mx, yc = y-my (forced 0 outside image)
//   ncc = Sxy / (sqrt(Sxx*Syy) + 25e-8),  S* = 5x5 sums of products
//   out = mean_c(ncc)

#define HH 512
#define WW 512
#define CHAN 3
#define SSTRIP 32
#define NSTRIPS (HH / SSTRIP)          // 16
#define OUTCOLS 56
#define NGROUPS 10                     // 10*56 = 560 >= 512
#define NBATCH 16
#define NCTAS (NGROUPS * NSTRIPS * NBATCH)   // 2560
#define PSTRIDE 58                     // plane row stride (even -> float2 STS)

__global__ __launch_bounds__(96, 8)
void zncc_warp_kernel(const float* __restrict__ xg,
                      const float* __restrict__ yg,
                      float* __restrict__ outg)
{
    __shared__ float plane[CHAN][SSTRIP][PSTRIDE];

    const unsigned FULL = 0xFFFFFFFFu;
    const int tid  = threadIdx.x;
    const int lane = tid & 31;
    const int ch   = tid >> 5;          // warp id == channel

    const int task  = blockIdx.x;
    const int b     = task / (NGROUPS * NSTRIPS);
    const int rem   = task - b * (NGROUPS * NSTRIPS);
    const int strip = rem / NGROUPS;
    const int g     = rem - strip * NGROUPS;

    const int r0  = strip * SSTRIP;
    const int gcA = g * OUTCOLS - 4 + 2 * lane;   // even
    const int gcB = gcA + 1;
    const float mA = (gcA >= 0 && gcA < WW) ? 1.0f : 0.0f;
    const float mB = (gcB >= 0 && gcB < WW) ? 1.0f : 0.0f;
    const bool outLane = (lane >= 2) && (lane <= 29) && (gcA < WW);
    const int gca_c = min(max(gcA, 0), WW - 2);   // clamped, float2-safe
    const int pcol  = 2 * lane - 4;               // plane column for col A

    const float inv25 = 1.0f / 25.0f;
    const float inv3  = 1.0f / 3.0f;

    const float* xb = xg + (size_t)(b * CHAN + ch) * (HH * WW);
    const float* yb = yg + (size_t)(b * CHAN + ch) * (HH * WW);

    // ring buffers (indices static after unroll-by-5)
    float hxA[5], hxB[5], hyA[5], hyB[5];
    float qxyA[5], qxyB[5], qxxA[5], qxxB[5], qyyA[5], qyyB[5];
    #pragma unroll
    for (int i = 0; i < 5; i++) {
        hxA[i] = hxB[i] = hyA[i] = hyB[i] = 0.f;
        qxyA[i] = qxyB[i] = qxxA[i] = qxxB[i] = qyyA[i] = qyyB[i] = 0.f;
    }
    float sHxA = 0.f, sHxB = 0.f, sHyA = 0.f, sHyB = 0.f;
    float sQxyA = 0.f, sQxyB = 0.f, sQxxA = 0.f, sQxxB = 0.f, sQyyA = 0.f, sQyyB = 0.f;
    // 2-deep shift pipeline for raw center values (need row t-2 at step t)
    float pxA1 = 0.f, pxA2 = 0.f, pxB1 = 0.f, pxB2 = 0.f;
    float pyA1 = 0.f, pyA2 = 0.f, pyB1 = 0.f, pyB2 = 0.f;

    // ---- 2-deep prefetch staging ----
    // st0 = row t (consumed this step), st1 = row t+1 (in flight / staged)
    const float* xp = xb + (ptrdiff_t)(r0 - 2) * WW + gca_c;  // row t+2 target
    const float* yp = yb + (ptrdiff_t)(r0 - 2) * WW + gca_c;
    float2 nx0 = make_float2(0.f, 0.f), ny0 = make_float2(0.f, 0.f);
    float2 nx1 = make_float2(0.f, 0.f), ny1 = make_float2(0.f, 0.f);
    if (r0 - 4 >= 0) {
        nx0 = *(const float2*)(xp - 2 * WW);
        ny0 = *(const float2*)(yp - 2 * WW);
    }
    if (r0 - 3 >= 0) {
        nx1 = *(const float2*)(xp - WW);
        ny1 = *(const float2*)(yp - WW);
    }
    int tr = r0 - 2;                    // row index of next load target

    for (int sb = 0; sb < SSTRIP + 8; sb += 5) {
        #pragma unroll
        for (int k = 0; k < 5; k++) {
            const int s = sb + k;                 // s % 5 == k
            const int t = r0 - 4 + s;             // raw row consumed now

            // ---- consume staged row t; shift; load row t+2 ----
            float vxA = nx0.x * mA, vxB = nx0.y * mB;
            float vyA = ny0.x * mA, vyB = ny0.y * mB;
            nx0 = nx1; ny0 = ny1;
            if ((unsigned)tr < (unsigned)HH) {    // warp-uniform
                nx1 = *(const float2*)xp;
                ny1 = *(const float2*)yp;
            } else {
                nx1 = make_float2(0.f, 0.f);
                ny1 = make_float2(0.f, 0.f);
            }
            xp += WW; yp += WW; tr++;

            // ---- horizontal 5-sums of x,y via shuffles ----
            float vxAm = __shfl_up_sync(FULL, vxA, 1);
            float vxBm = __shfl_up_sync(FULL, vxB, 1);
            float vxAp = __shfl_down_sync(FULL, vxA, 1);
            float vxBp = __shfl_down_sync(FULL, vxB, 1);
            float cx   = vxBm + vxA + vxB + vxAp;
            float hxEn = cx + vxAm;               // col A (2l)
            float hxOn = cx + vxBp;               // col B (2l+1)

            float vyAm = __shfl_up_sync(FULL, vyA, 1);
            float vyBm = __shfl_up_sync(FULL, vyB, 1);
            float vyAp = __shfl_down_sync(FULL, vyA, 1);
            float vyBp = __shfl_down_sync(FULL, vyB, 1);
            float cy   = vyBm + vyA + vyB + vyAp;
            float hyEn = cy + vyAm;
            float hyOn = cy + vyBp;

            // ---- vertical sliding sums of h ----
            sHxA += hxEn - hxA[k]; hxA[k] = hxEn;
            sHxB += hxOn - hxB[k]; hxB[k] = hxOn;
            sHyA += hyEn - hyA[k]; hyA[k] = hyEn;
            sHyB += hyOn - hyB[k]; hyB[k] = hyOn;

            if (s >= 4) {
                const int tm = t - 2;             // row whose mean is ready
                const float rm = (tm >= 0 && tm < HH) ? 1.0f : 0.0f;

                // centered values at row tm (raw from 2 steps ago)
                float xcA = fmaf(sHxA, -inv25, pxA2) * (mA * rm);
                float xcB = fmaf(sHxB, -inv25, pxB2) * (mB * rm);
                float ycA = fmaf(sHyA, -inv25, pyA2) * (mA * rm);
                float ycB = fmaf(sHyB, -inv25, pyB2) * (mB * rm);

                // neighbors of xc,yc
                float xcAm = __shfl_up_sync(FULL, xcA, 1);
                float xcBm = __shfl_up_sync(FULL, xcB, 1);
                float xcAp = __shfl_down_sync(FULL, xcA, 1);
                float xcBp = __shfl_down_sync(FULL, xcB, 1);
                float ycAm = __shfl_up_sync(FULL, ycA, 1);
                float ycBm = __shfl_up_sync(FULL, ycB, 1);
                float ycAp = __shfl_down_sync(FULL, ycA, 1);
                float ycBp = __shfl_down_sync(FULL, ycB, 1);

                // horizontal 5-sums of products (shared middle-4 term)
                float c4xy = xcBm * ycBm + xcA * ycA + xcB * ycB + xcAp * ycAp;
                float qxyE = c4xy + xcAm * ycAm;
                float qxyO = c4xy + xcBp * ycBp;
                float c4xx = xcBm * xcBm + xcA * xcA + xcB * xcB + xcAp * xcAp;
                float qxxE = c4xx + xcAm * xcAm;
                float qxxO = c4xx + xcBp * xcBp;
                float c4yy = ycBm * ycBm + ycA * ycA + ycB * ycB + ycAp * ycAp;
                float qyyE = c4yy + ycAm * ycAm;
                float qyyO = c4yy + ycBp * ycBp;

                // vertical sliding sums of q
                sQxyA += qxyE - qxyA[k]; qxyA[k] = qxyE;
                sQxyB += qxyO - qxyB[k]; qxyB[k] = qxyO;
                sQxxA += qxxE - qxxA[k]; qxxA[k] = qxxE;
                sQxxB += qxxO - qxxB[k]; qxxB[k] = qxxO;
                sQyyA += qyyE - qyyA[k]; qyyA[k] = qyyE;
                sQyyB += qyyO - qyyB[k]; qyyB[k] = qyyO;

                if (s >= 8) {
                    const int row = s - 8;        // output row within strip
                    float dA = sqrtf(fmaxf(sQxxA * sQyyA, 0.f)) + 2.5e-7f;
                    float dB = sqrtf(fmaxf(sQxxB * sQyyB, 0.f)) + 2.5e-7f;
                    float nA = __fdividef(sQxyA, dA);
                    float nB = __fdividef(sQxyB, dB);
                    if (outLane) {
                        *(float2*)&plane[ch][row][pcol] = make_float2(nA, nB);
                    }
                }
            }

            // shift raw-center pipeline
            pxA2 = pxA1; pxA1 = vxA;
            pxB2 = pxB1; pxB1 = vxB;
            pyA2 = pyA1; pyA1 = vyA;
            pyB2 = pyB1; pyB1 = vyB;
        }
    }

    __syncthreads();

    // ---- combine channels in fixed order (deterministic) and write out ----
    float* outp = outg + (size_t)b * (HH * WW) + (size_t)r0 * WW + g * OUTCOLS;
    for (int idx = tid; idx < SSTRIP * OUTCOLS; idx += 96) {
        int row = idx / OUTCOLS;
        int c   = idx - row * OUTCOLS;
        if (g * OUTCOLS + c < WW) {
            float v = (plane[0][row][c] + plane[1][row][c] + plane[2][row][c]) * inv3;
            outp[(size_t)row * WW + c] = v;
        }
    }
}

extern "C" void kernel_launch(void* const* d_in, const int* in_sizes, int n_in,
                              void* d_out, int out_size)
{
    const float* x = (const float*)d_in[0];
    const float* y = (const float*)d_in[1];
    float* out = (float*)d_out;

    zncc_warp_kernel<<<NCTAS, 96>>>(x, y, out);
}

// round 8
// speedup vs baseline: 1.1244x; 1.1244x over previous
#include <cuda_runtime.h>

// ZNCC fused, warp-per-channel sliding-window version (R5 pipeline, verbatim),
// with __launch_bounds__(96,9) to fit 9 CTAs/SM -> 2 clean scheduling waves.
// CTA = 96 threads = 3 warps; warp w handles channel w of one
// (batch, strip, col-group) tile: 64 raw cols (2/lane) x 32 output rows.
// Per-channel NCC rows -> smem plane; one __syncthreads; fixed-order combine.
//
// math per pixel (zero-padded 5x5 means):
//   mx = box(x), my = box(y); xc = x-mx, yc = y-my (forced 0 outside image)
//   ncc = Sxy / (sqrt(Sxx*Syy) + 25e-8),  S* = 5x5 sums of products
//   out = mean_c(ncc)

#define HH 512
#define WW 512
#define CHAN 3
#define SSTRIP 32
#define NSTRIPS (HH / SSTRIP)          // 16
#define OUTCOLS 56
#define NGROUPS 10                     // 10*56 = 560 >= 512
#define NBATCH 16
#define NCTAS (NGROUPS * NSTRIPS * NBATCH)   // 2560
#define PSTRIDE 58                     // plane row stride (even -> float2 STS)

__global__ __launch_bounds__(96, 9)
void zncc_warp_kernel(const float* __restrict__ xg,
                      const float* __restrict__ yg,
                      float* __restrict__ outg)
{
    __shared__ float plane[CHAN][SSTRIP][PSTRIDE];

    const unsigned FULL = 0xFFFFFFFFu;
    const int tid  = threadIdx.x;
    const int lane = tid & 31;
    const int ch   = tid >> 5;          // warp id == channel

    const int task  = blockIdx.x;
    const int b     = task / (NGROUPS * NSTRIPS);
    const int rem   = task - b * (NGROUPS * NSTRIPS);
    const int strip = rem / NGROUPS;
    const int g     = rem - strip * NGROUPS;

    const int r0  = strip * SSTRIP;
    const int gcA = g * OUTCOLS - 4 + 2 * lane;   // even
    const int gcB = gcA + 1;
    const float mA = (gcA >= 0 && gcA < WW) ? 1.0f : 0.0f;
    const float mB = (gcB >= 0 && gcB < WW) ? 1.0f : 0.0f;
    const bool outLane = (lane >= 2) && (lane <= 29) && (gcA < WW);
    const int gca_c = min(max(gcA, 0), WW - 2);   // clamped, float2-safe
    const int pcol  = 2 * lane - 4;               // plane column for col A

    const float inv25 = 1.0f / 25.0f;
    const float inv3  = 1.0f / 3.0f;

    const float* xb = xg + (size_t)(b * CHAN + ch) * (HH * WW);
    const float* yb = yg + (size_t)(b * CHAN + ch) * (HH * WW);

    // ring buffers (indices static after unroll-by-5)
    float hxA[5], hxB[5], hyA[5], hyB[5];
    float qxyA[5], qxyB[5], qxxA[5], qxxB[5], qyyA[5], qyyB[5];
    #pragma unroll
    for (int i = 0; i < 5; i++) {
        hxA[i] = hxB[i] = hyA[i] = hyB[i] = 0.f;
        qxyA[i] = qxyB[i] = qxxA[i] = qxxB[i] = qyyA[i] = qyyB[i] = 0.f;
    }
    float sHxA = 0.f, sHxB = 0.f, sHyA = 0.f, sHyB = 0.f;
    float sQxyA = 0.f, sQxyB = 0.f, sQxxA = 0.f, sQxxB = 0.f, sQyyA = 0.f, sQyyB = 0.f;
    // 2-deep shift pipeline for raw center values (need row t-2 at step t)
    float pxA1 = 0.f, pxA2 = 0.f, pxB1 = 0.f, pxB2 = 0.f;
    float pyA1 = 0.f, pyA2 = 0.f, pyB1 = 0.f, pyB2 = 0.f;

    // staged next-row values (software prefetch)
    float2 nvx = make_float2(0.f, 0.f), nvy = make_float2(0.f, 0.f);
    {
        const int t0 = r0 - 4;
        if (t0 >= 0) {
            nvx = *(const float2*)(xb + (size_t)t0 * WW + gca_c);
            nvy = *(const float2*)(yb + (size_t)t0 * WW + gca_c);
        }
    }

    for (int sb = 0; sb < SSTRIP + 8; sb += 5) {
        #pragma unroll
        for (int k = 0; k < 5; k++) {
            const int s = sb + k;                 // s % 5 == k
            const int t = r0 - 4 + s;             // raw row consumed now

            // ---- consume staged row t, issue loads for row t+1 ----
            float vxA = nvx.x * mA, vxB = nvx.y * mB;
            float vyA = nvy.x * mA, vyB = nvy.y * mB;
            {
                const int tn = t + 1;             // warp-uniform
                if (tn >= 0 && tn < HH) {
                    nvx = *(const float2*)(xb + (size_t)tn * WW + gca_c);
                    nvy = *(const float2*)(yb + (size_t)tn * WW + gca_c);
                } else {
                    nvx = make_float2(0.f, 0.f);
                    nvy = make_float2(0.f, 0.f);
                }
            }
            if (t < 0) { vxA = vxB = vyA = vyB = 0.f; }  // above-image rows

            // ---- horizontal 5-sums of x,y via shuffles ----
            float vxAm = __shfl_up_sync(FULL, vxA, 1);
            float vxBm = __shfl_up_sync(FULL, vxB, 1);
            float vxAp = __shfl_down_sync(FULL, vxA, 1);
            float vxBp = __shfl_down_sync(FULL, vxB, 1);
            float cx   = vxBm + vxA + vxB + vxAp;
            float hxEn = cx + vxAm;               // col A (2l)
            float hxOn = cx + vxBp;               // col B (2l+1)

            float vyAm = __shfl_up_sync(FULL, vyA, 1);
            float vyBm = __shfl_up_sync(FULL, vyB, 1);
            float vyAp = __shfl_down_sync(FULL, vyA, 1);
            float vyBp = __shfl_down_sync(FULL, vyB, 1);
            float cy   = vyBm + vyA + vyB + vyAp;
            float hyEn = cy + vyAm;
            float hyOn = cy + vyBp;

            // ---- vertical sliding sums of h ----
            sHxA += hxEn - hxA[k]; hxA[k] = hxEn;
            sHxB += hxOn - hxB[k]; hxB[k] = hxOn;
            sHyA += hyEn - hyA[k]; hyA[k] = hyEn;
            sHyB += hyOn - hyB[k]; hyB[k] = hyOn;

            if (s >= 4) {
                const int tm = t - 2;             // row whose mean is ready
                const float rm = (tm >= 0 && tm < HH) ? 1.0f : 0.0f;

                // centered values at row tm (raw from 2 steps ago)
                float xcA = fmaf(sHxA, -inv25, pxA2) * (mA * rm);
                float xcB = fmaf(sHxB, -inv25, pxB2) * (mB * rm);
                float ycA = fmaf(sHyA, -inv25, pyA2) * (mA * rm);
                float ycB = fmaf(sHyB, -inv25, pyB2) * (mB * rm);

                // neighbors of xc,yc
                float xcAm = __shfl_up_sync(FULL, xcA, 1);
                float xcBm = __shfl_up_sync(FULL, xcB, 1);
                float xcAp = __shfl_down_sync(FULL, xcA, 1);
                float xcBp = __shfl_down_sync(FULL, xcB, 1);
                float ycAm = __shfl_up_sync(FULL, ycA, 1);
                float ycBm = __shfl_up_sync(FULL, ycB, 1);
                float ycAp = __shfl_down_sync(FULL, ycA, 1);
                float ycBp = __shfl_down_sync(FULL, ycB, 1);

                // horizontal 5-sums of products (shared middle-4 term)
                float c4xy = xcBm * ycBm + xcA * ycA + xcB * ycB + xcAp * ycAp;
                float qxyE = c4xy + xcAm * ycAm;
                float qxyO = c4xy + xcBp * ycBp;
                float c4xx = xcBm * xcBm + xcA * xcA + xcB * xcB + xcAp * xcAp;
                float qxxE = c4xx + xcAm * xcAm;
                float qxxO = c4xx + xcBp * xcBp;
                float c4yy = ycBm * ycBm + ycA * ycA + ycB * ycB + ycAp * ycAp;
                float qyyE = c4yy + ycAm * ycAm;
                float qyyO = c4yy + ycBp * ycBp;

                // vertical sliding sums of q
                sQxyA += qxyE - qxyA[k]; qxyA[k] = qxyE;
                sQxyB += qxyO - qxyB[k]; qxyB[k] = qxyO;
                sQxxA += qxxE - qxxA[k]; qxxA[k] = qxxE;
                sQxxB += qxxO - qxxB[k]; qxxB[k] = qxxO;
                sQyyA += qyyE - qyyA[k]; qyyA[k] = qyyE;
                sQyyB += qyyO - qyyB[k]; qyyB[k] = qyyO;

                if (s >= 8) {
                    const int row = s - 8;        // output row within strip
                    float dA = sqrtf(fmaxf(sQxxA * sQyyA, 0.f)) + 2.5e-7f;
                    float dB = sqrtf(fmaxf(sQxxB * sQyyB, 0.f)) + 2.5e-7f;
                    float nA = __fdividef(sQxyA, dA);
                    float nB = __fdividef(sQxyB, dB);
                    if (outLane) {
                        *(float2*)&plane[ch][row][pcol] = make_float2(nA, nB);
                    }
                }
            }

            // shift raw-center pipeline
            pxA2 = pxA1; pxA1 = vxA;
            pxB2 = pxB1; pxB1 = vxB;
            pyA2 = pyA1; pyA1 = vyA;
            pyB2 = pyB1; pyB1 = vyB;
        }
    }

    __syncthreads();

    // ---- combine channels in fixed order (deterministic) and write out ----
    float* outp = outg + (size_t)b * (HH * WW) + (size_t)r0 * WW + g * OUTCOLS;
    for (int idx = tid; idx < SSTRIP * OUTCOLS; idx += 96) {
        int row = idx / OUTCOLS;
        int c   = idx - row * OUTCOLS;
        if (g * OUTCOLS + c < WW) {
            float v = (plane[0][row][c] + plane[1][row][c] + plane[2][row][c]) * inv3;
            outp[(size_t)row * WW + c] = v;
        }
    }
}

extern "C" void kernel_launch(void* const* d_in, const int* in_sizes, int n_in,
                              void* d_out, int out_size)
{
    const float* x = (const float*)d_in[0];
    const float* y = (const float*)d_in[1];
    float* out = (float*)d_out;

    zncc_warp_kernel<<<NCTAS, 96>>>(x, y, out);
}

// round 9
// speedup vs baseline: 1.4106x; 1.2545x over previous
#include <cuda_runtime.h>

// ZNCC fused, warp-per-channel sliding-window version (R5 pipeline, verbatim
// mainloop). Per-channel combine plane moved from shared memory to a
// __device__ global scratch buffer -> smem = 0 -> occupancy becomes
// warp-limited (21 CTAs/SM), whole grid fits in one wave.
// CTA = 96 threads = 3 warps; warp w handles channel w of one
// (batch, strip, col-group) tile: 64 raw cols (2/lane) x 32 output rows.
//
// math per pixel (zero-padded 5x5 means):
//   mx = box(x), my = box(y); xc = x-mx, yc = y-my (forced 0 outside image)
//   ncc = Sxy / (sqrt(Sxx*Syy) + 25e-8),  S* = 5x5 sums of products
//   out = mean_c(ncc)

#define HH 512
#define WW 512
#define CHAN 3
#define SSTRIP 32
#define NSTRIPS (HH / SSTRIP)          // 16
#define OUTCOLS 56
#define NGROUPS 10                     // 10*56 = 560 >= 512
#define NBATCH 16
#define NCTAS (NGROUPS * NSTRIPS * NBATCH)   // 2560

#define CSTR (NBATCH * HH * WW)        // per-channel scratch stride

// global scratch: per-channel NCC maps (3 x 16 x 512 x 512 floats = 50 MB)
__device__ float g_scratch[CHAN * CSTR];

__global__ __launch_bounds__(96, 7)
void zncc_warp_kernel(const float* __restrict__ xg,
                      const float* __restrict__ yg,
                      float* __restrict__ outg)
{
    const unsigned FULL = 0xFFFFFFFFu;
    const int tid  = threadIdx.x;
    const int lane = tid & 31;
    const int ch   = tid >> 5;          // warp id == channel

    const int task  = blockIdx.x;
    const int b     = task / (NGROUPS * NSTRIPS);
    const int rem   = task - b * (NGROUPS * NSTRIPS);
    const int strip = rem / NGROUPS;
    const int g     = rem - strip * NGROUPS;

    const int r0  = strip * SSTRIP;
    const int gcA = g * OUTCOLS - 4 + 2 * lane;   // even
    const int gcB = gcA + 1;
    const float mA = (gcA >= 0 && gcA < WW) ? 1.0f : 0.0f;
    const float mB = (gcB >= 0 && gcB < WW) ? 1.0f : 0.0f;
    const bool outLane = (lane >= 2) && (lane <= 29) && (gcA < WW);
    const int gca_c = min(max(gcA, 0), WW - 2);   // clamped, float2-safe

    const float inv25 = 1.0f / 25.0f;
    const float inv3  = 1.0f / 3.0f;

    const float* xb = xg + (size_t)(b * CHAN + ch) * (HH * WW);
    const float* yb = yg + (size_t)(b * CHAN + ch) * (HH * WW);

    // scratch write base for this warp's channel/batch
    float* scr = g_scratch + (size_t)ch * CSTR + (size_t)b * (HH * WW);

    // ring buffers (indices static after unroll-by-5)
    float hxA[5], hxB[5], hyA[5], hyB[5];
    float qxyA[5], qxyB[5], qxxA[5], qxxB[5], qyyA[5], qyyB[5];
    #pragma unroll
    for (int i = 0; i < 5; i++) {
        hxA[i] = hxB[i] = hyA[i] = hyB[i] = 0.f;
        qxyA[i] = qxyB[i] = qxxA[i] = qxxB[i] = qyyA[i] = qyyB[i] = 0.f;
    }
    float sHxA = 0.f, sHxB = 0.f, sHyA = 0.f, sHyB = 0.f;
    float sQxyA = 0.f, sQxyB = 0.f, sQxxA = 0.f, sQxxB = 0.f, sQyyA = 0.f, sQyyB = 0.f;
    // 2-deep shift pipeline for raw center values (need row t-2 at step t)
    float pxA1 = 0.f, pxA2 = 0.f, pxB1 = 0.f, pxB2 = 0.f;
    float pyA1 = 0.f, pyA2 = 0.f, pyB1 = 0.f, pyB2 = 0.f;

    // staged next-row values (software prefetch)
    float2 nvx = make_float2(0.f, 0.f), nvy = make_float2(0.f, 0.f);
    {
        const int t0 = r0 - 4;
        if (t0 >= 0) {
            nvx = *(const float2*)(xb + (size_t)t0 * WW + gca_c);
            nvy = *(const float2*)(yb + (size_t)t0 * WW + gca_c);
        }
    }

    for (int sb = 0; sb < SSTRIP + 8; sb += 5) {
        #pragma unroll
        for (int k = 0; k < 5; k++) {
            const int s = sb + k;                 // s % 5 == k
            const int t = r0 - 4 + s;             // raw row consumed now

            // ---- consume staged row t, issue loads for row t+1 ----
            float vxA = nvx.x * mA, vxB = nvx.y * mB;
            float vyA = nvy.x * mA, vyB = nvy.y * mB;
            {
                const int tn = t + 1;             // warp-uniform
                if (tn >= 0 && tn < HH) {
                    nvx = *(const float2*)(xb + (size_t)tn * WW + gca_c);
                    nvy = *(const float2*)(yb + (size_t)tn * WW + gca_c);
                } else {
                    nvx = make_float2(0.f, 0.f);
                    nvy = make_float2(0.f, 0.f);
                }
            }
            if (t < 0) { vxA = vxB = vyA = vyB = 0.f; }  // above-image rows

            // ---- horizontal 5-sums of x,y via shuffles ----
            float vxAm = __shfl_up_sync(FULL, vxA, 1);
            float vxBm = __shfl_up_sync(FULL, vxB, 1);
            float vxAp = __shfl_down_sync(FULL, vxA, 1);
            float vxBp = __shfl_down_sync(FULL, vxB, 1);
            float cx   = vxBm + vxA + vxB + vxAp;
            float hxEn = cx + vxAm;               // col A (2l)
            float hxOn = cx + vxBp;               // col B (2l+1)

            float vyAm = __shfl_up_sync(FULL, vyA, 1);
            float vyBm = __shfl_up_sync(FULL, vyB, 1);
            float vyAp = __shfl_down_sync(FULL, vyA, 1);
            float vyBp = __shfl_down_sync(FULL, vyB, 1);
            float cy   = vyBm + vyA + vyB + vyAp;
            float hyEn = cy + vyAm;
            float hyOn = cy + vyBp;

            // ---- vertical sliding sums of h ----
            sHxA += hxEn - hxA[k]; hxA[k] = hxEn;
            sHxB += hxOn - hxB[k]; hxB[k] = hxOn;
            sHyA += hyEn - hyA[k]; hyA[k] = hyEn;
            sHyB += hyOn - hyB[k]; hyB[k] = hyOn;

            if (s >= 4) {
                const int tm = t - 2;             // row whose mean is ready
                const float rm = (tm >= 0 && tm < HH) ? 1.0f : 0.0f;

                // centered values at row tm (raw from 2 steps ago)
                float xcA = fmaf(sHxA, -inv25, pxA2) * (mA * rm);
                float xcB = fmaf(sHxB, -inv25, pxB2) * (mB * rm);
                float ycA = fmaf(sHyA, -inv25, pyA2) * (mA * rm);
                float ycB = fmaf(sHyB, -inv25, pyB2) * (mB * rm);

                // neighbors of xc,yc
                float xcAm = __shfl_up_sync(FULL, xcA, 1);
                float xcBm = __shfl_up_sync(FULL, xcB, 1);
                float xcAp = __shfl_down_sync(FULL, xcA, 1);
                float xcBp = __shfl_down_sync(FULL, xcB, 1);
                float ycAm = __shfl_up_sync(FULL, ycA, 1);
                float ycBm = __shfl_up_sync(FULL, ycB, 1);
                float ycAp = __shfl_down_sync(FULL, ycA, 1);
                float ycBp = __shfl_down_sync(FULL, ycB, 1);

                // horizontal 5-sums of products (shared middle-4 term)
                float c4xy = xcBm * ycBm + xcA * ycA + xcB * ycB + xcAp * ycAp;
                float qxyE = c4xy + xcAm * ycAm;
                float qxyO = c4xy + xcBp * ycBp;
                float c4xx = xcBm * xcBm + xcA * xcA + xcB * xcB + xcAp * xcAp;
                float qxxE = c4xx + xcAm * xcAm;
                float qxxO = c4xx + xcBp * xcBp;
                float c4yy = ycBm * ycBm + ycA * ycA + ycB * ycB + ycAp * ycAp;
                float qyyE = c4yy + ycAm * ycAm;
                float qyyO = c4yy + ycBp * ycBp;

                // vertical sliding sums of q
                sQxyA += qxyE - qxyA[k]; qxyA[k] = qxyE;
                sQxyB += qxyO - qxyB[k]; qxyB[k] = qxyO;
                sQxxA += qxxE - qxxA[k]; qxxA[k] = qxxE;
                sQxxB += qxxO - qxxB[k]; qxxB[k] = qxxO;
                sQyyA += qyyE - qyyA[k]; qyyA[k] = qyyE;
                sQyyB += qyyO - qyyB[k]; qyyB[k] = qyyO;

                if (s >= 8) {
                    const int row = s - 8;        // output row within strip
                    float dA = sqrtf(fmaxf(sQxxA * sQyyA, 0.f)) + 2.5e-7f;
                    float dB = sqrtf(fmaxf(sQxxB * sQyyB, 0.f)) + 2.5e-7f;
                    float nA = __fdividef(sQxyA, dA);
                    float nB = __fdividef(sQxyB, dB);
                    if (outLane) {
                        *(float2*)(scr + (size_t)(r0 + row) * WW + gcA) =
                            make_float2(nA, nB);
                    }
                }
            }

            // shift raw-center pipeline
            pxA2 = pxA1; pxA1 = vxA;
            pxB2 = pxB1; pxB1 = vxB;
            pyA2 = pyA1; pyA1 = vyA;
            pyB2 = pyB1; pyB1 = vyB;
        }
    }

    __syncthreads();   // fences the CTA's global scratch writes

    // ---- combine channels in fixed order (deterministic) and write out ----
    const float* s0 = g_scratch + 0 * (size_t)CSTR + (size_t)b * (HH * WW);
    const float* s1 = g_scratch + 1 * (size_t)CSTR + (size_t)b * (HH * WW);
    const float* s2 = g_scratch + 2 * (size_t)CSTR + (size_t)b * (HH * WW);
    float* outp = outg + (size_t)b * (HH * WW);
    for (int idx = tid; idx < SSTRIP * OUTCOLS; idx += 96) {
        int row = idx / OUTCOLS;
        int c   = idx - row * OUTCOLS;
        int gcol = g * OUTCOLS + c;
        if (gcol < WW) {
            size_t off = (size_t)(r0 + row) * WW + gcol;
            float v = (s0[off] + s1[off] + s2[off]) * inv3;
            outp[off] = v;
        }
    }
}

extern "C" void kernel_launch(void* const* d_in, const int* in_sizes, int n_in,
                              void* d_out, int out_size)
{
    const float* x = (const float*)d_in[0];
    const float* y = (const float*)d_in[1];
    float* out = (float*)d_out;

    zncc_warp_kernel<<<NCTAS, 96>>>(x, y, out);
}

// round 10
// speedup vs baseline: 1.6792x; 1.1905x over previous
#include <cuda_runtime.h>

// ZNCC fused, warp-per-channel sliding-window (R5 pipeline) with
// interior/boundary template specialization.
// CTA = 96 threads = 3 warps; warp w handles channel w of one
// (batch, strip, col-group) tile: 64 raw cols (2/lane) x 32 output rows.
// Per-channel NCC rows -> smem plane; one __syncthreads; fixed-order combine.
//
// math per pixel (zero-padded 5x5 means):
//   mx = box(x), my = box(y); xc = x-mx, yc = y-my (forced 0 outside image)
//   ncc = Sxy / (sqrt(Sxx*Syy) + 25e-8),  S* = 5x5 sums of products
//   out = mean_c(ncc)

#define HH 512
#define WW 512
#define CHAN 3
#define SSTRIP 32
#define NSTRIPS (HH / SSTRIP)          // 16
#define OUTCOLS 56
#define NGROUPS 10                     // 10*56 = 560 >= 512
#define NBATCH 16
#define NCTAS (NGROUPS * NSTRIPS * NBATCH)   // 2560
#define PSTRIDE 58                     // plane row stride (even -> float2 ops)

// CINT: all 64 raw columns inside image (groups 1..8)
// RINT: all raw rows r0-4 .. r0+35 inside image (strips 1..14)
template<bool CINT, bool RINT>
__device__ __forceinline__ void zncc_tile(
    const float* __restrict__ xb, const float* __restrict__ yb,
    float (*plane)[PSTRIDE],
    int r0, int lane, float mA, float mB, bool outLane, int gca_c, int pcol)
{
    const unsigned FULL = 0xFFFFFFFFu;
    const float inv25 = 1.0f / 25.0f;

    // ring buffers (indices static after unroll-by-5)
    float hxA[5], hxB[5], hyA[5], hyB[5];
    float qxyA[5], qxyB[5], qxxA[5], qxxB[5], qyyA[5], qyyB[5];
    #pragma unroll
    for (int i = 0; i < 5; i++) {
        hxA[i] = hxB[i] = hyA[i] = hyB[i] = 0.f;
        qxyA[i] = qxyB[i] = qxxA[i] = qxxB[i] = qyyA[i] = qyyB[i] = 0.f;
    }
    float sHxA = 0.f, sHxB = 0.f, sHyA = 0.f, sHyB = 0.f;
    float sQxyA = 0.f, sQxyB = 0.f, sQxxA = 0.f, sQxxB = 0.f, sQyyA = 0.f, sQyyB = 0.f;
    // 2-deep shift pipeline for raw center values (need row t-2 at step t)
    float pxA1 = 0.f, pxA2 = 0.f, pxB1 = 0.f, pxB2 = 0.f;
    float pyA1 = 0.f, pyA2 = 0.f, pyB1 = 0.f, pyB2 = 0.f;

    // staged next-row values (software prefetch)
    float2 nvx = make_float2(0.f, 0.f), nvy = make_float2(0.f, 0.f);
    {
        const int t0 = r0 - 4;
        if (RINT || t0 >= 0) {
            nvx = *(const float2*)(xb + (size_t)t0 * WW + gca_c);
            nvy = *(const float2*)(yb + (size_t)t0 * WW + gca_c);
        }
    }

    for (int sb = 0; sb < SSTRIP + 8; sb += 5) {
        #pragma unroll
        for (int k = 0; k < 5; k++) {
            const int s = sb + k;                 // s % 5 == k
            const int t = r0 - 4 + s;             // raw row consumed now

            // ---- consume staged row t, issue loads for row t+1 ----
            float vxA, vxB, vyA, vyB;
            if (CINT) {
                vxA = nvx.x; vxB = nvx.y;
                vyA = nvy.x; vyB = nvy.y;
            } else {
                vxA = nvx.x * mA; vxB = nvx.y * mB;
                vyA = nvy.x * mA; vyB = nvy.y * mB;
            }
            {
                const int tn = t + 1;             // warp-uniform
                if (RINT || (unsigned)tn < (unsigned)HH) {
                    nvx = *(const float2*)(xb + (size_t)tn * WW + gca_c);
                    nvy = *(const float2*)(yb + (size_t)tn * WW + gca_c);
                } else {
                    nvx = make_float2(0.f, 0.f);
                    nvy = make_float2(0.f, 0.f);
                }
            }
            if (!RINT) {
                if (t < 0) { vxA = vxB = vyA = vyB = 0.f; }  // above-image rows
            }

            // ---- horizontal 5-sums of x,y via shuffles ----
            float vxAm = __shfl_up_sync(FULL, vxA, 1);
            float vxBm = __shfl_up_sync(FULL, vxB, 1);
            float vxAp = __shfl_down_sync(FULL, vxA, 1);
            float vxBp = __shfl_down_sync(FULL, vxB, 1);
            float cx   = vxBm + vxA + vxB + vxAp;
            float hxEn = cx + vxAm;               // col A (2l)
            float hxOn = cx + vxBp;               // col B (2l+1)

            float vyAm = __shfl_up_sync(FULL, vyA, 1);
            float vyBm = __shfl_up_sync(FULL, vyB, 1);
            float vyAp = __shfl_down_sync(FULL, vyA, 1);
            float vyBp = __shfl_down_sync(FULL, vyB, 1);
            float cy   = vyBm + vyA + vyB + vyAp;
            float hyEn = cy + vyAm;
            float hyOn = cy + vyBp;

            // ---- vertical sliding sums of h ----
            sHxA += hxEn - hxA[k]; hxA[k] = hxEn;
            sHxB += hxOn - hxB[k]; hxB[k] = hxOn;
            sHyA += hyEn - hyA[k]; hyA[k] = hyEn;
            sHyB += hyOn - hyB[k]; hyB[k] = hyOn;

            if (s >= 4) {
                // centered values at row tm = t-2 (raw from 2 steps ago)
                float xcA, xcB, ycA, ycB;
                if (CINT && RINT) {
                    xcA = fmaf(sHxA, -inv25, pxA2);
                    xcB = fmaf(sHxB, -inv25, pxB2);
                    ycA = fmaf(sHyA, -inv25, pyA2);
                    ycB = fmaf(sHyB, -inv25, pyB2);
                } else {
                    const int tm = t - 2;
                    const float rm = (RINT || ((unsigned)tm < (unsigned)HH)) ? 1.0f : 0.0f;
                    const float fmA = CINT ? rm : mA * rm;
                    const float fmB = CINT ? rm : mB * rm;
                    xcA = fmaf(sHxA, -inv25, pxA2) * fmA;
                    xcB = fmaf(sHxB, -inv25, pxB2) * fmB;
                    ycA = fmaf(sHyA, -inv25, pyA2) * fmA;
                    ycB = fmaf(sHyB, -inv25, pyB2) * fmB;
                }

                // neighbors of xc,yc
                float xcAm = __shfl_up_sync(FULL, xcA, 1);
                float xcBm = __shfl_up_sync(FULL, xcB, 1);
                float xcAp = __shfl_down_sync(FULL, xcA, 1);
                float xcBp = __shfl_down_sync(FULL, xcB, 1);
                float ycAm = __shfl_up_sync(FULL, ycA, 1);
                float ycBm = __shfl_up_sync(FULL, ycB, 1);
                float ycAp = __shfl_down_sync(FULL, ycA, 1);
                float ycBp = __shfl_down_sync(FULL, ycB, 1);

                // horizontal 5-sums of products (shared middle-4 term)
                float c4xy = xcBm * ycBm + xcA * ycA + xcB * ycB + xcAp * ycAp;
                float qxyE = c4xy + xcAm * ycAm;
                float qxyO = c4xy + xcBp * ycBp;
                float c4xx = xcBm * xcBm + xcA * xcA + xcB * xcB + xcAp * xcAp;
                float qxxE = c4xx + xcAm * xcAm;
                float qxxO = c4xx + xcBp * xcBp;
                float c4yy = ycBm * ycBm + ycA * ycA + ycB * ycB + ycAp * ycAp;
                float qyyE = c4yy + ycAm * ycAm;
                float qyyO = c4yy + ycBp * ycBp;

                // vertical sliding sums of q
                sQxyA += qxyE - qxyA[k]; qxyA[k] = qxyE;
                sQxyB += qxyO - qxyB[k]; qxyB[k] = qxyO;
                sQxxA += qxxE - qxxA[k]; qxxA[k] = qxxE;
                sQxxB += qxxO - qxxB[k]; qxxB[k] = qxxO;
                sQyyA += qyyE - qyyA[k]; qyyA[k] = qyyE;
                sQyyB += qyyO - qyyB[k]; qyyB[k] = qyyO;

                if (s >= 8) {
                    const int row = s - 8;        // output row within strip
                    float dA = sqrtf(fmaxf(sQxxA * sQyyA, 0.f)) + 2.5e-7f;
                    float dB = sqrtf(fmaxf(sQxxB * sQyyB, 0.f)) + 2.5e-7f;
                    float nA = __fdividef(sQxyA, dA);
                    float nB = __fdividef(sQxyB, dB);
                    if (outLane) {
                        *(float2*)&plane[row][pcol] = make_float2(nA, nB);
                    }
                }
            }

            // shift raw-center pipeline
            pxA2 = pxA1; pxA1 = vxA;
            pxB2 = pxB1; pxB1 = vxB;
            pyA2 = pyA1; pyA1 = vyA;
            pyB2 = pyB1; pyB1 = vyB;
        }
    }
}

__global__ __launch_bounds__(96, 7)
void zncc_warp_kernel(const float* __restrict__ xg,
                      const float* __restrict__ yg,
                      float* __restrict__ outg)
{
    __shared__ float plane[CHAN][SSTRIP][PSTRIDE];

    const int tid  = threadIdx.x;
    const int lane = tid & 31;
    const int ch   = tid >> 5;          // warp id == channel

    const int task  = blockIdx.x;
    const int b     = task / (NGROUPS * NSTRIPS);
    const int rem   = task - b * (NGROUPS * NSTRIPS);
    const int strip = rem / NGROUPS;
    const int g     = rem - strip * NGROUPS;

    const int r0  = strip * SSTRIP;
    const int gcA = g * OUTCOLS - 4 + 2 * lane;   // even
    const int gcB = gcA + 1;
    const float mA = (gcA >= 0 && gcA < WW) ? 1.0f : 0.0f;
    const float mB = (gcB >= 0 && gcB < WW) ? 1.0f : 0.0f;
    const bool outLane = (lane >= 2) && (lane <= 29) && (gcA < WW);
    const int gca_c = min(max(gcA, 0), WW - 2);   // clamped, float2-safe
    const int pcol  = 2 * lane - 4;               // plane column for col A

    const float inv3 = 1.0f / 3.0f;

    const float* xb = xg + (size_t)(b * CHAN + ch) * (HH * WW);
    const float* yb = yg + (size_t)(b * CHAN + ch) * (HH * WW);

    // interior flags (uniform per CTA)
    const bool cint = (g >= 1) && (g <= 8);               // all 64 cols in-image
    const bool rint = (strip >= 1) && (strip <= NSTRIPS - 2);  // all rows in-image

    if (cint) {
        if (rint) zncc_tile<true,  true >(xb, yb, plane[ch], r0, lane, mA, mB, outLane, gca_c, pcol);
        else      zncc_tile<true,  false>(xb, yb, plane[ch], r0, lane, mA, mB, outLane, gca_c, pcol);
    } else {
        if (rint) zncc_tile<false, true >(xb, yb, plane[ch], r0, lane, mA, mB, outLane, gca_c, pcol);
        else      zncc_tile<false, false>(xb, yb, plane[ch], r0, lane, mA, mB, outLane, gca_c, pcol);
    }

    __syncthreads();

    // ---- combine channels in fixed order (deterministic), float2 I/O ----
    float* outp = outg + (size_t)b * (HH * WW) + (size_t)r0 * WW + g * OUTCOLS;
    for (int idx = tid; idx < SSTRIP * (OUTCOLS / 2); idx += 96) {
        int row = idx / (OUTCOLS / 2);
        int c2  = idx - row * (OUTCOLS / 2);
        int col = 2 * c2;
        if (g * OUTCOLS + col < WW) {   // col even, WW even -> col+1 also in
            float2 p0 = *(const float2*)&plane[0][row][col];
            float2 p1 = *(const float2*)&plane[1][row][col];
            float2 p2 = *(const float2*)&plane[2][row][col];
            float2 v;
            v.x = (p0.x + p1.x + p2.x) * inv3;
            v.y = (p0.y + p1.y + p2.y) * inv3;
            *(float2*)&outp[(size_t)row * WW + col] = v;
        }
    }
}

extern "C" void kernel_launch(void* const* d_in, const int* in_sizes, int n_in,
                              void* d_out, int out_size)
{
    const float* x = (const float*)d_in[0];
    const float* y = (const float*)d_in[1];
    float* out = (float*)d_out;

    zncc_warp_kernel<<<NCTAS, 96>>>(x, y, out);
}